// round 6
// baseline (speedup 1.0000x reference)
#include <cuda_runtime.h>

#define BATCH  32
#define HW     3136
#define C      256
#define C4     64            // C/4
#define CR     64
#define PPC    16            // pixels per chunk
#define CHUNKS 196           // HW / PPC
#define BPG    16            // batches per group (x_group = 51.4 MB < L2)
#define GROUPS 2

// Scratch (allocation-free per harness rules)
__device__ float g_partial[BATCH * CHUNKS * C];
__device__ float g_gate[BATCH * C];

// ---------------------------------------------------------------------------
// gap_kernel: grid = (CHUNKS, BPG) = 3136 blocks, block = 256, lean (~26 regs,
// occ 86%). 4 independent LDG.128 per thread, L1-bypass / L2-allocate so the
// group's x stays hot in L2 for mul. Smem reduce across 4 pixel subgroups.
// ---------------------------------------------------------------------------
__global__ __launch_bounds__(256) void gap_kernel(const float4* __restrict__ x4,
                                                  int b0)
{
    const int chunk = blockIdx.x;
    const int b     = b0 + blockIdx.y;
    const int tid   = threadIdx.x;
    const int c4    = tid & (C4 - 1);
    const int pr    = tid >> 6;

    const size_t base = ((size_t)(b * HW + chunk * PPC + pr)) * C4 + c4;

    float4 v0 = __ldcg(&x4[base]);
    float4 v1 = __ldcg(&x4[base +  4 * C4]);
    float4 v2 = __ldcg(&x4[base +  8 * C4]);
    float4 v3 = __ldcg(&x4[base + 12 * C4]);

    float4 acc;
    acc.x = (v0.x + v1.x) + (v2.x + v3.x);
    acc.y = (v0.y + v1.y) + (v2.y + v3.y);
    acc.z = (v0.z + v1.z) + (v2.z + v3.z);
    acc.w = (v0.w + v1.w) + (v2.w + v3.w);

    __shared__ float4 red[256];
    red[tid] = acc;
    __syncthreads();

    if (tid < C4) {
        float4 a  = red[tid];
        float4 b1 = red[tid + 64];
        float4 c1 = red[tid + 128];
        float4 d1 = red[tid + 192];
        a.x += b1.x + c1.x + d1.x;
        a.y += b1.y + c1.y + d1.y;
        a.z += b1.z + c1.z + d1.z;
        a.w += b1.w + c1.w + d1.w;
        ((float4*)g_partial)[(b * CHUNKS + chunk) * C4 + tid] = a;
    }
}

// ---------------------------------------------------------------------------
// fc_kernel: BPG blocks x 256 threads. Reduce 196 partials -> mean -> w1 ->
// relu6 -> w2 -> hsigmoid -> gate.
// ---------------------------------------------------------------------------
__global__ __launch_bounds__(256) void fc_kernel(const float* __restrict__ w1,
                                                 const float* __restrict__ w2,
                                                 int b0)
{
    const int b = b0 + blockIdx.x;
    const int t = threadIdx.x;

    __shared__ float s[C];
    __shared__ float h[CR];

    float sum = 0.0f;
#pragma unroll 4
    for (int k = 0; k < CHUNKS; ++k) {
        sum += __ldcg(&g_partial[(b * CHUNKS + k) * C + t]);
    }
    s[t] = sum * (1.0f / (float)HW);
    __syncthreads();

    if (t < CR) {
        float acc = 0.0f;
#pragma unroll 8
        for (int c = 0; c < C; ++c) {
            acc += s[c] * w1[c * CR + t];
        }
        h[t] = fminf(fmaxf(acc, 0.0f), 6.0f);
    }
    __syncthreads();

    float acc = 0.0f;
#pragma unroll
    for (int r = 0; r < CR; ++r) {
        acc += h[r] * w2[r * C + t];
    }
    g_gate[b * C + t] = fminf(fmaxf(acc + 3.0f, 0.0f), 6.0f) * (1.0f / 6.0f);
}

// ---------------------------------------------------------------------------
// mul_kernel: grid = (CHUNKS, BPG) = 3136 blocks, block = 256, lean regs.
// x-reads hit L2 (gap just streamed this 51.4MB group); gate in a register;
// streaming stores (evict-first) so the write stream doesn't evict x.
// ---------------------------------------------------------------------------
__global__ __launch_bounds__(256) void mul_kernel(const float4* __restrict__ x4,
                                                  float4* __restrict__ out4,
                                                  int b0)
{
    const int chunk = blockIdx.x;
    const int b     = b0 + blockIdx.y;
    const int tid   = threadIdx.x;
    const int c4    = tid & (C4 - 1);
    const int pr    = tid >> 6;

    const float4 gv = __ldcg(&((const float4*)g_gate)[b * C4 + c4]);
    const size_t base = ((size_t)(b * HW + chunk * PPC + pr)) * C4 + c4;

    float4 v0 = __ldcg(&x4[base]);
    float4 v1 = __ldcg(&x4[base +  4 * C4]);
    float4 v2 = __ldcg(&x4[base +  8 * C4]);
    float4 v3 = __ldcg(&x4[base + 12 * C4]);

    v0.x *= gv.x; v0.y *= gv.y; v0.z *= gv.z; v0.w *= gv.w;
    v1.x *= gv.x; v1.y *= gv.y; v1.z *= gv.z; v1.w *= gv.w;
    v2.x *= gv.x; v2.y *= gv.y; v2.z *= gv.z; v2.w *= gv.w;
    v3.x *= gv.x; v3.y *= gv.y; v3.z *= gv.z; v3.w *= gv.w;

    __stcs(&out4[base],           v0);
    __stcs(&out4[base +  4 * C4], v1);
    __stcs(&out4[base +  8 * C4], v2);
    __stcs(&out4[base + 12 * C4], v3);
}

extern "C" void kernel_launch(void* const* d_in, const int* in_sizes, int n_in,
                              void* d_out, int out_size) {
    const float* x  = (const float*)d_in[0];
    const float* w1 = (const float*)d_in[1];
    const float* w2 = (const float*)d_in[2];
    float* out      = (float*)d_out;

    dim3 grid(CHUNKS, BPG);
    for (int g = 0; g < GROUPS; ++g) {
        const int b0 = g * BPG;
        gap_kernel<<<grid, 256>>>((const float4*)x, b0);
        fc_kernel<<<BPG, 256>>>(w1, w2, b0);
        mul_kernel<<<grid, 256>>>((const float4*)x, (float4*)out, b0);
    }
}